// round 2
// baseline (speedup 1.0000x reference)
#include <cuda_runtime.h>

// ---------------------------------------------------------------------------
// Problem constants
// ---------------------------------------------------------------------------
constexpr int IMH = 512;
constexpr int IMW = 512;
constexpr int NK  = 8;     // zbuf layers

typedef unsigned long long ull;

// ---------------------------------------------------------------------------
// f32x2 packed-FMA helpers (FFMA2: 2x fp32 FMA per issue slot on sm_103a)
// ---------------------------------------------------------------------------
__device__ __forceinline__ ull pk2(float v) {
    ull r; unsigned u = __float_as_uint(v);
    asm("mov.b64 %0, {%1, %1};" : "=l"(r) : "r"(u));
    return r;
}
__device__ __forceinline__ void fma2(ull& d, ull a, ull b) {
    asm("fma.rn.f32x2 %0, %1, %2, %0;" : "+l"(d) : "l"(a), "l"(b));
}
__device__ __forceinline__ float2 upk(ull v) {
    unsigned lo, hi;
    asm("mov.b64 {%0, %1}, %2;" : "=r"(lo), "=r"(hi) : "l"(v));
    return make_float2(__uint_as_float(lo), __uint_as_float(hi));
}

// ---------------------------------------------------------------------------
// Scratch buffers (static device globals -- no cudaMalloc allowed)
// ---------------------------------------------------------------------------
__device__ float g_t1[(size_t)NK * IMH * IMW * 32];   // sup1 out   (256 MB)
__device__ float g_fm[(size_t)NK * IMH * IMW * 64];   // [fz | fc]  (512 MB)
__device__ float g_t2[(size_t)NK * IMH * IMW * 64];   // mpn1 out   (512 MB)
__device__ float g_fuse[(size_t)IMH * IMW * NK];      // fused img  (8 MB)
__device__ float g_t3[(size_t)IMH * IMW * 32];        // un1 out    (32 MB)

// ---------------------------------------------------------------------------
// Fused 4-layer MLP. One block = 64 consecutive x for fixed (k, y).
// SMEM: two buffers, row stride 136 floats per point.
//   bufA cols 128..130 : dirs (persist),  col 131 : z (mask)   — never
//   overwritten by the 128-wide layer outputs.
// ---------------------------------------------------------------------------
template<int KIN, bool RELU>
__device__ __forceinline__ void mlp_layer128(const float* __restrict__ bufIn,
                                             float* __restrict__ bufOut,
                                             const float* __restrict__ Wg,
                                             const float* __restrict__ bg, int tid)
{
    int jg = tid & 15, pg = tid >> 4;       // 16 j-groups x 16 p-groups
    int j0 = jg * 8,  p0 = pg * 4;          // 8 outputs x 4 points per thread
    ull acc[4][4];
    ulonglong2 bb0 = *(const ulonglong2*)(bg + j0);
    ulonglong2 bb1 = *(const ulonglong2*)(bg + j0 + 4);
#pragma unroll
    for (int i = 0; i < 4; i++) { acc[i][0]=bb0.x; acc[i][1]=bb0.y; acc[i][2]=bb1.x; acc[i][3]=bb1.y; }
#pragma unroll 4
    for (int kk = 0; kk < KIN; kk++) {
        ulonglong2 w0 = *(const ulonglong2*)(Wg + kk*128 + j0);
        ulonglong2 w1 = *(const ulonglong2*)(Wg + kk*128 + j0 + 4);
#pragma unroll
        for (int i = 0; i < 4; i++) {
            ull av = pk2(bufIn[(p0+i)*136 + kk]);
            fma2(acc[i][0], av, w0.x); fma2(acc[i][1], av, w0.y);
            fma2(acc[i][2], av, w1.x); fma2(acc[i][3], av, w1.y);
        }
    }
#pragma unroll
    for (int i = 0; i < 4; i++) {
        float* orow = bufOut + (p0+i)*136 + j0;
#pragma unroll
        for (int h = 0; h < 4; h++) {
            float2 o = upk(acc[i][h]);
            if (RELU) { o.x = fmaxf(o.x, 0.f); o.y = fmaxf(o.y, 0.f); }
            orow[2*h] = o.x; orow[2*h+1] = o.y;
        }
    }
}

__global__ __launch_bounds__(256) void mlp_kernel(
    const float* __restrict__ ray, const float* __restrict__ zbufs,
    const float* __restrict__ W1, const float* __restrict__ b1,
    const float* __restrict__ W2, const float* __restrict__ b2,
    const float* __restrict__ W3, const float* __restrict__ b3,
    const float* __restrict__ W4, const float* __restrict__ b4,
    float* __restrict__ fm)
{
    extern __shared__ float sm[];
    float* bufA = sm;
    float* bufB = sm + 64 * 136;
    int tid = threadIdx.x;
    int x0 = blockIdx.x * 64, y = blockIdx.y, k = blockIdx.z;

    if (tid < 64) {
        int x = x0 + tid;
        const float* r = ray + ((long long)y * IMW + x) * 7;
        float dx = r[3], dy = r[4], dz = r[5];
        float z = zbufs[((long long)y * IMW + x) * NK + k];
        float t = z / r[6];
        float* row = bufA + tid * 136;
        row[0] = r[0] + dx * t; row[1] = r[1] + dy * t; row[2] = r[2] + dz * t;
        row[128] = dx; row[129] = dy; row[130] = dz; row[131] = z;
    }
    __syncthreads();
    mlp_layer128<3,   true>(bufA, bufB, W1, b1, tid);
    __syncthreads();
    mlp_layer128<128, true>(bufB, bufA, W2, b2, tid);   // dirs/z at cols 128..131 survive
    __syncthreads();
    mlp_layer128<131, true>(bufA, bufB, W3, b3, tid);   // concat([h, dirs]) @ W3
    __syncthreads();
    {   // layer 4: 128 -> 32, no relu, masked write to fm[...,0:32]
        int jg = tid & 3, p = tid >> 2;
        int j0 = jg * 8;
        ull acc[4];
        ulonglong2 bb0 = *(const ulonglong2*)(b4 + j0);
        ulonglong2 bb1 = *(const ulonglong2*)(b4 + j0 + 4);
        acc[0] = bb0.x; acc[1] = bb0.y; acc[2] = bb1.x; acc[3] = bb1.y;
        const float* rowi = bufB + p * 136;
#pragma unroll 4
        for (int kk = 0; kk < 128; kk++) {
            ulonglong2 w0 = *(const ulonglong2*)(W4 + kk*32 + j0);
            ulonglong2 w1 = *(const ulonglong2*)(W4 + kk*32 + j0 + 4);
            ull av = pk2(rowi[kk]);
            fma2(acc[0], av, w0.x); fma2(acc[1], av, w0.y);
            fma2(acc[2], av, w1.x); fma2(acc[3], av, w1.y);
        }
        bool live = bufA[p*136 + 131] > 0.f;
        long long ob = ((long long)(k * IMH + y) * IMW + x0 + p) * 64 + j0;
#pragma unroll
        for (int h = 0; h < 4; h++) {
            float2 o = upk(acc[h]);
            fm[ob + 2*h]     = live ? o.x : 0.f;
            fm[ob + 2*h + 1] = live ? o.y : 0.f;
        }
    }
}

// ---------------------------------------------------------------------------
// Generic 3x3 SAME conv, NHWC, register-tiled.
// 16x8 pixel tile per block, 128 threads = 32 pixel-quads x 4 cout-groups.
// ACT: 0 = none, 1 = relu, 2 = sigmoid + cumprod-composite epilogue.
// Input addr  = z*inZStr  + (gy*W+gx)*inPixStr  + ci
// Output addr = z*outZStr + (gy*W+gx)*outPixStr + outChOff + co
// ---------------------------------------------------------------------------
template<int CIN, int COUT, int ACT>
__global__ __launch_bounds__(128) void conv3x3_kernel(
    const float* __restrict__ in, const float* __restrict__ wt,
    const float* __restrict__ bias, float* __restrict__ out,
    long long inZStr, int inPixStr,
    long long outZStr, int outPixStr, int outChOff,
    const float* __restrict__ fmp, float* __restrict__ fusep)
{
    constexpr int TX = 16, TY = 8;
    constexpr int CCH = (CIN < 16) ? CIN : 16;
    constexpr int NCH = CIN / CCH;
    constexpr int CO_T = COUT / 4;
    constexpr int CO_H = CO_T / 2;       // f32x2 pairs per thread

    __shared__ __align__(16) float ish[CCH][TY+2][TX+2];
    __shared__ __align__(16) float wsh[9][CCH][COUT];

    int tid = threadIdx.x;
    int z = blockIdx.z;
    int bx = blockIdx.x * TX, by = blockIdx.y * TY;
    int cog = tid >> 5, pixg = tid & 31;
    int px0 = (pixg & 3) * 4, py = pixg >> 2;
    int co0 = cog * CO_T;

    ull acc[4][CO_H];
#pragma unroll
    for (int p = 0; p < 4; p++)
#pragma unroll
        for (int h = 0; h < CO_H; h++) acc[p][h] = 0ULL;

#pragma unroll 1
    for (int ch = 0; ch < NCH; ch++) {
        int cbase = ch * CCH;
        if (ch > 0) __syncthreads();
        // stage input tile (with halo, zero-padded at borders)
        for (int e = tid; e < CCH * (TY+2) * (TX+2); e += 128) {
            int ci = e / ((TY+2)*(TX+2));
            int rem = e - ci * ((TY+2)*(TX+2));
            int yy = rem / (TX+2), xx = rem - yy * (TX+2);
            int gy = by + yy - 1, gx = bx + xx - 1;
            float v = 0.f;
            if (gy >= 0 && gy < IMH && gx >= 0 && gx < IMW)
                v = in[(long long)z * inZStr + (long long)(gy * IMW + gx) * inPixStr + cbase + ci];
            ish[ci][yy][xx] = v;
        }
        // stage weight chunk (HWIO)
        for (int e = tid; e < 9 * CCH * COUT; e += 128) {
            int tap = e / (CCH * COUT);
            int rem = e - tap * (CCH * COUT);
            int ci = rem / COUT, co = rem - ci * COUT;
            wsh[tap][ci][co] = wt[((long long)tap * CIN + cbase + ci) * COUT + co];
        }
        __syncthreads();
#pragma unroll 1
        for (int ci = 0; ci < CCH; ci++) {
#pragma unroll
            for (int dy = 0; dy < 3; dy++) {
                const float* row = &ish[ci][py + dy][px0];
                ull v[6];
#pragma unroll
                for (int m = 0; m < 6; m++) v[m] = pk2(row[m]);
#pragma unroll
                for (int dxx = 0; dxx < 3; dxx++) {
                    const ulonglong2* wp = (const ulonglong2*)&wsh[dy*3 + dxx][ci][co0];
#pragma unroll
                    for (int h2 = 0; h2 < CO_H/2; h2++) {
                        ulonglong2 wv = wp[h2];
#pragma unroll
                        for (int p = 0; p < 4; p++) {
                            fma2(acc[p][2*h2],     v[p + dxx], wv.x);
                            fma2(acc[p][2*h2 + 1], v[p + dxx], wv.y);
                        }
                    }
                }
            }
        }
    }

    int gy = by + py;
    if constexpr (ACT != 2) {
#pragma unroll
        for (int p = 0; p < 4; p++) {
            int gx = bx + px0 + p;
            long long ob = (long long)z * outZStr + (long long)(gy * IMW + gx) * outPixStr
                         + outChOff + co0;
#pragma unroll
            for (int h = 0; h < CO_H; h++) {
                float2 o = upk(acc[p][h]);
                float c0 = o.x + bias[co0 + 2*h];
                float c1 = o.y + bias[co0 + 2*h + 1];
                if (ACT == 1) { c0 = fmaxf(c0, 0.f); c1 = fmaxf(c1, 0.f); }
                out[ob + 2*h] = c0; out[ob + 2*h + 1] = c1;
            }
        }
    } else {
        // sigmoid -> SMEM (reuse wsh), then per-pixel cumprod compositing
        __syncthreads();                       // everyone done reading wsh
        float* msh = &wsh[0][0][0];            // 128 pixels x stride 65
#pragma unroll
        for (int p = 0; p < 4; p++) {
            int lp = py * 16 + px0 + p;
#pragma unroll
            for (int h = 0; h < CO_H; h++) {
                float2 o = upk(acc[p][h]);
                msh[lp*65 + co0 + 2*h]     = 1.f / (1.f + __expf(-(o.x + bias[co0 + 2*h])));
                msh[lp*65 + co0 + 2*h + 1] = 1.f / (1.f + __expf(-(o.y + bias[co0 + 2*h + 1])));
            }
        }
        __syncthreads();
        int lp = tid;                          // 128 threads == 128 pixels
        int py2 = lp >> 4, px2 = lp & 15;
        int gy2 = by + py2, gx2 = bx + px2;
        const float* fr = fmp + ((long long)(z * IMH + gy2) * IMW + gx2) * 64;
        float a = 1.f, fs = 0.f;
#pragma unroll
        for (int c = 0; c < 64; c += 4) {
            float4 f = *(const float4*)(fr + c);
            float m0 = msh[lp*65 + c],     m1 = msh[lp*65 + c + 1];
            float m2 = msh[lp*65 + c + 2], m3 = msh[lp*65 + c + 3];
            fs += f.x * m0 * a; a *= (1.f - m0);
            fs += f.y * m1 * a; a *= (1.f - m1);
            fs += f.z * m2 * a; a *= (1.f - m2);
            fs += f.w * m3 * a; a *= (1.f - m3);
        }
        fusep[(long long)(gy2 * IMW + gx2) * NK + z] = fs;
    }
}

// ---------------------------------------------------------------------------
// Final tiny conv: 32 -> 3 (un2). One thread per pixel.
// ---------------------------------------------------------------------------
__global__ __launch_bounds__(256) void conv_small_kernel(
    const float* __restrict__ in, const float* __restrict__ wt,
    const float* __restrict__ bias, float* __restrict__ out)
{
    __shared__ float wsh[9 * 32 * 3];
    int tid = threadIdx.x;
    for (int e = tid; e < 9 * 32 * 3; e += 256) wsh[e] = wt[e];
    __syncthreads();
    int pix = blockIdx.x * 256 + tid;
    int gy = pix / IMW, gx = pix - gy * IMW;
    float a0 = bias[0], a1 = bias[1], a2 = bias[2];
#pragma unroll
    for (int dy = 0; dy < 3; dy++) {
        int iy = gy + dy - 1;
        if (iy < 0 || iy >= IMH) continue;
#pragma unroll
        for (int dxx = 0; dxx < 3; dxx++) {
            int ix = gx + dxx - 1;
            if (ix < 0 || ix >= IMW) continue;
            const float* ip = in + ((long long)iy * IMW + ix) * 32;
            const float* wp = &wsh[(dy*3 + dxx) * 32 * 3];
#pragma unroll
            for (int ci = 0; ci < 32; ci++) {
                float v = ip[ci];
                a0 += v * wp[ci*3 + 0];
                a1 += v * wp[ci*3 + 1];
                a2 += v * wp[ci*3 + 2];
            }
        }
    }
    out[(long long)pix * 3 + 0] = a0;
    out[(long long)pix * 3 + 1] = a1;
    out[(long long)pix * 3 + 2] = a2;
}

// ---------------------------------------------------------------------------
// Launcher
// ---------------------------------------------------------------------------
extern "C" void kernel_launch(void* const* d_in, const int* in_sizes, int n_in,
                              void* d_out, int out_size)
{
    (void)in_sizes; (void)n_in; (void)out_size;
    const float* colors = (const float*)d_in[0];
    const float* ray    = (const float*)d_in[1];
    const float* zbufs  = (const float*)d_in[2];
    const float* W1 = (const float*)d_in[3],  * b1 = (const float*)d_in[4];
    const float* W2 = (const float*)d_in[5],  * b2 = (const float*)d_in[6];
    const float* W3 = (const float*)d_in[7],  * b3 = (const float*)d_in[8];
    const float* W4 = (const float*)d_in[9],  * b4 = (const float*)d_in[10];
    const float* ks1 = (const float*)d_in[11], * bs1 = (const float*)d_in[12];
    const float* ks2 = (const float*)d_in[13], * bs2 = (const float*)d_in[14];
    const float* km1 = (const float*)d_in[15], * bm1 = (const float*)d_in[16];
    const float* km2 = (const float*)d_in[17], * bm2 = (const float*)d_in[18];
    const float* ku1 = (const float*)d_in[19], * bu1 = (const float*)d_in[20];
    const float* ku2 = (const float*)d_in[21], * bu2 = (const float*)d_in[22];
    float* out = (float*)d_out;

    float *t1, *fm, *t2, *fuse, *t3;
    cudaGetSymbolAddress((void**)&t1,   g_t1);
    cudaGetSymbolAddress((void**)&fm,   g_fm);
    cudaGetSymbolAddress((void**)&t2,   g_t2);
    cudaGetSymbolAddress((void**)&fuse, g_fuse);
    cudaGetSymbolAddress((void**)&t3,   g_t3);

    const long long P32 = (long long)IMH * IMW * 32;
    const long long P64 = (long long)IMH * IMW * 64;

    // MLP -> fm[...,0:32]   (needs 68 KB dynamic smem)
    static int smem_set = 0;
    if (!smem_set) {
        cudaFuncSetAttribute(mlp_kernel, cudaFuncAttributeMaxDynamicSharedMemorySize,
                             2 * 64 * 136 * (int)sizeof(float));
        smem_set = 1;
    }
    mlp_kernel<<<dim3(IMW/64, IMH, NK), 256, 2 * 64 * 136 * sizeof(float)>>>(
        ray, zbufs, W1, b1, W2, b2, W3, b3, W4, b4, fm);

    dim3 cgrid(IMW/16, IMH/8, NK);
    // sup1: colors[k-slice] (3 ch) -> t1 (32 ch), relu
    conv3x3_kernel<3, 32, 1><<<cgrid, 128>>>(
        colors, ks1, bs1, t1, /*inZStr=*/3, /*inPixStr=*/3*NK,
        P32, 32, 0, nullptr, nullptr);
    // sup2: t1 -> fm[...,32:64], no act
    conv3x3_kernel<32, 32, 0><<<cgrid, 128>>>(
        t1, ks2, bs2, fm, P32, 32,
        P64, 64, 32, nullptr, nullptr);
    // mpn1: fm -> t2, relu
    conv3x3_kernel<64, 64, 1><<<cgrid, 128>>>(
        fm, km1, bm1, t2, P64, 64,
        P64, 64, 0, nullptr, nullptr);
    // mpn2: t2 -> sigmoid -> composite with fm -> fuse[H,W,K]
    conv3x3_kernel<64, 64, 2><<<cgrid, 128>>>(
        t2, km2, bm2, nullptr, P64, 64,
        0, 0, 0, fm, fuse);
    // un1: fuse (8 ch) -> t3 (32 ch), relu
    conv3x3_kernel<8, 32, 1><<<dim3(IMW/16, IMH/8, 1), 128>>>(
        fuse, ku1, bu1, t3, 0, NK,
        0, 32, 0, nullptr, nullptr);
    // un2: t3 -> out (3 ch)
    conv_small_kernel<<<(IMH*IMW)/256, 256>>>(t3, ku2, bu2, out);
}

// round 12
// speedup vs baseline: 1.2820x; 1.2820x over previous
#include <cuda_runtime.h>

// ---------------------------------------------------------------------------
// Problem constants
// ---------------------------------------------------------------------------
constexpr int IMH = 512;
constexpr int IMW = 512;
constexpr int NK  = 8;     // zbuf layers

typedef unsigned long long ull;

// ---------------------------------------------------------------------------
// f32x2 packed-FMA helpers (FFMA2: 2x fp32 FMA per issue slot on sm_103a)
// ---------------------------------------------------------------------------
__device__ __forceinline__ ull pk2(float v) {
    ull r; unsigned u = __float_as_uint(v);
    asm("mov.b64 %0, {%1, %1};" : "=l"(r) : "r"(u));
    return r;
}
__device__ __forceinline__ void fma2(ull& d, ull a, ull b) {
    asm("fma.rn.f32x2 %0, %1, %2, %0;" : "+l"(d) : "l"(a), "l"(b));
}
__device__ __forceinline__ float2 upk(ull v) {
    unsigned lo, hi;
    asm("mov.b64 {%0, %1}, %2;" : "=r"(lo), "=r"(hi) : "l"(v));
    return make_float2(__uint_as_float(lo), __uint_as_float(hi));
}

// ---------------------------------------------------------------------------
// Scratch buffers (static device globals -- no cudaMalloc allowed)
// ---------------------------------------------------------------------------
__device__ float g_t1[(size_t)NK * IMH * IMW * 32];   // sup1 out
__device__ float g_fm[(size_t)NK * IMH * IMW * 64];   // [fz | fc]
__device__ float g_t2[(size_t)NK * IMH * IMW * 64];   // mpn1 out
__device__ float g_fuse[(size_t)IMH * IMW * NK];      // fused img
__device__ float g_t3[(size_t)IMH * IMW * 32];        // un1 out

// ---------------------------------------------------------------------------
// Fused 4-layer MLP. One block = 64 consecutive x for fixed (k, y).
// SMEM: two buffers, row stride 136 floats per point.
//   bufA cols 128..130 : dirs (persist),  col 131 : z (mask)
// ---------------------------------------------------------------------------
template<int KIN, bool RELU>
__device__ __forceinline__ void mlp_layer128(const float* __restrict__ bufIn,
                                             float* __restrict__ bufOut,
                                             const float* __restrict__ Wg,
                                             const float* __restrict__ bg, int tid)
{
    int jg = tid & 15, pg = tid >> 4;       // 16 j-groups x 16 p-groups
    int j0 = jg * 8,  p0 = pg * 4;          // 8 outputs x 4 points per thread
    ull acc[4][4];
    ulonglong2 bb0 = *(const ulonglong2*)(bg + j0);
    ulonglong2 bb1 = *(const ulonglong2*)(bg + j0 + 4);
#pragma unroll
    for (int i = 0; i < 4; i++) { acc[i][0]=bb0.x; acc[i][1]=bb0.y; acc[i][2]=bb1.x; acc[i][3]=bb1.y; }

    constexpr int KV = KIN & ~3;            // vectorized portion
#pragma unroll 2
    for (int kk = 0; kk < KV; kk += 4) {
        float4 a[4];
#pragma unroll
        for (int i = 0; i < 4; i++)
            a[i] = *(const float4*)&bufIn[(p0+i)*136 + kk];
#pragma unroll
        for (int q = 0; q < 4; q++) {
            ulonglong2 w0 = *(const ulonglong2*)(Wg + (kk+q)*128 + j0);
            ulonglong2 w1 = *(const ulonglong2*)(Wg + (kk+q)*128 + j0 + 4);
#pragma unroll
            for (int i = 0; i < 4; i++) {
                float s = (q==0) ? a[i].x : (q==1) ? a[i].y : (q==2) ? a[i].z : a[i].w;
                ull av = pk2(s);
                fma2(acc[i][0], av, w0.x); fma2(acc[i][1], av, w0.y);
                fma2(acc[i][2], av, w1.x); fma2(acc[i][3], av, w1.y);
            }
        }
    }
#pragma unroll
    for (int kk = KV; kk < KIN; kk++) {     // scalar tail (KIN=3 or 131)
        ulonglong2 w0 = *(const ulonglong2*)(Wg + kk*128 + j0);
        ulonglong2 w1 = *(const ulonglong2*)(Wg + kk*128 + j0 + 4);
#pragma unroll
        for (int i = 0; i < 4; i++) {
            ull av = pk2(bufIn[(p0+i)*136 + kk]);
            fma2(acc[i][0], av, w0.x); fma2(acc[i][1], av, w0.y);
            fma2(acc[i][2], av, w1.x); fma2(acc[i][3], av, w1.y);
        }
    }
#pragma unroll
    for (int i = 0; i < 4; i++) {
        float* orow = bufOut + (p0+i)*136 + j0;
#pragma unroll
        for (int h = 0; h < 4; h += 2) {
            float2 o0 = upk(acc[i][h]);
            float2 o1 = upk(acc[i][h+1]);
            if (RELU) {
                o0.x = fmaxf(o0.x, 0.f); o0.y = fmaxf(o0.y, 0.f);
                o1.x = fmaxf(o1.x, 0.f); o1.y = fmaxf(o1.y, 0.f);
            }
            *(float4*)(orow + 2*h) = make_float4(o0.x, o0.y, o1.x, o1.y);
        }
    }
}

__global__ __launch_bounds__(256, 3) void mlp_kernel(
    const float* __restrict__ ray, const float* __restrict__ zbufs,
    const float* __restrict__ W1, const float* __restrict__ b1,
    const float* __restrict__ W2, const float* __restrict__ b2,
    const float* __restrict__ W3, const float* __restrict__ b3,
    const float* __restrict__ W4, const float* __restrict__ b4,
    float* __restrict__ fm)
{
    extern __shared__ float sm[];
    float* bufA = sm;
    float* bufB = sm + 64 * 136;
    int tid = threadIdx.x;
    int x0 = blockIdx.x * 64, y = blockIdx.y, k = blockIdx.z;

    if (tid < 64) {
        int x = x0 + tid;
        const float* r = ray + ((long long)y * IMW + x) * 7;
        float dx = r[3], dy = r[4], dz = r[5];
        float z = zbufs[((long long)y * IMW + x) * NK + k];
        float t = z / r[6];
        float* row = bufA + tid * 136;
        row[0] = r[0] + dx * t; row[1] = r[1] + dy * t; row[2] = r[2] + dz * t;
        row[128] = dx; row[129] = dy; row[130] = dz; row[131] = z;
    }
    __syncthreads();
    mlp_layer128<3,   true>(bufA, bufB, W1, b1, tid);
    __syncthreads();
    mlp_layer128<128, true>(bufB, bufA, W2, b2, tid);   // dirs/z at 128..131 survive
    __syncthreads();
    mlp_layer128<131, true>(bufA, bufB, W3, b3, tid);   // concat([h, dirs]) @ W3
    __syncthreads();
    {   // layer 4: 128 -> 32, no relu, masked vectorized write to fm[...,0:32]
        int jg = tid & 3, p = tid >> 2;
        int j0 = jg * 8;
        ull acc[4];
        ulonglong2 bb0 = *(const ulonglong2*)(b4 + j0);
        ulonglong2 bb1 = *(const ulonglong2*)(b4 + j0 + 4);
        acc[0] = bb0.x; acc[1] = bb0.y; acc[2] = bb1.x; acc[3] = bb1.y;
        const float* rowi = bufB + p * 136;
#pragma unroll 2
        for (int kk = 0; kk < 128; kk += 4) {
            float4 a = *(const float4*)(rowi + kk);
#pragma unroll
            for (int q = 0; q < 4; q++) {
                ulonglong2 w0 = *(const ulonglong2*)(W4 + (kk+q)*32 + j0);
                ulonglong2 w1 = *(const ulonglong2*)(W4 + (kk+q)*32 + j0 + 4);
                float s = (q==0) ? a.x : (q==1) ? a.y : (q==2) ? a.z : a.w;
                ull av = pk2(s);
                fma2(acc[0], av, w0.x); fma2(acc[1], av, w0.y);
                fma2(acc[2], av, w1.x); fma2(acc[3], av, w1.y);
            }
        }
        bool live = bufA[p*136 + 131] > 0.f;
        long long ob = ((long long)(k * IMH + y) * IMW + x0 + p) * 64 + j0;
        float2 o0 = upk(acc[0]), o1 = upk(acc[1]), o2 = upk(acc[2]), o3 = upk(acc[3]);
        float4 v0 = live ? make_float4(o0.x, o0.y, o1.x, o1.y) : make_float4(0,0,0,0);
        float4 v1 = live ? make_float4(o2.x, o2.y, o3.x, o3.y) : make_float4(0,0,0,0);
        *(float4*)(fm + ob)     = v0;
        *(float4*)(fm + ob + 4) = v1;
    }
}

// ---------------------------------------------------------------------------
// Generic 3x3 SAME conv, NHWC, register-tiled.
// 16x8 pixel tile per block, 128 threads = 32 pixel-quads x 4 cout-groups.
// ACT: 0 = none, 1 = relu, 2 = sigmoid + cumprod-composite epilogue.
// ---------------------------------------------------------------------------
template<int CIN, int COUT, int ACT>
__global__ __launch_bounds__(128, 4) void conv3x3_kernel(
    const float* __restrict__ in, const float* __restrict__ wt,
    const float* __restrict__ bias, float* __restrict__ out,
    long long inZStr, int inPixStr,
    long long outZStr, int outPixStr, int outChOff,
    const float* __restrict__ fmp, float* __restrict__ fusep)
{
    constexpr int TX = 16, TY = 8;
    constexpr int CCH = (CIN < 16) ? CIN : 16;
    constexpr int NCH = CIN / CCH;
    constexpr int CO_T = COUT / 4;
    constexpr int CO_H = CO_T / 2;       // f32x2 pairs per thread
    constexpr int XPAD = 20;             // padded row (16B-aligned rows)

    __shared__ __align__(16) float ish[CCH][TY+2][XPAD];
    __shared__ __align__(16) float wsh[9][CCH][COUT];

    int tid = threadIdx.x;
    int z = blockIdx.z;
    int bx = blockIdx.x * TX, by = blockIdx.y * TY;
    int cog = tid >> 5, pixg = tid & 31;
    int px0 = (pixg & 3) * 4, py = pixg >> 2;
    int co0 = cog * CO_T;

    ull acc[4][CO_H];
#pragma unroll
    for (int p = 0; p < 4; p++)
#pragma unroll
        for (int h = 0; h < CO_H; h++) acc[p][h] = 0ULL;

#pragma unroll 1
    for (int ch = 0; ch < NCH; ch++) {
        int cbase = ch * CCH;
        if (ch > 0) __syncthreads();
        // ---- stage input tile (with halo, zero-padded at borders) ----
        if constexpr (CCH % 4 == 0) {
            constexpr int C4 = CCH / 4;
            for (int e = tid; e < (TY+2)*(TX+2)*C4; e += 128) {
                int c4 = e % C4, pix = e / C4;
                int yy = pix / (TX+2), xx = pix - yy * (TX+2);
                int gy = by + yy - 1, gx = bx + xx - 1;
                float4 v = make_float4(0.f, 0.f, 0.f, 0.f);
                if (gy >= 0 && gy < IMH && gx >= 0 && gx < IMW)
                    v = *(const float4*)&in[(long long)z * inZStr
                        + (long long)(gy * IMW + gx) * inPixStr + cbase + c4*4];
                ish[c4*4+0][yy][xx] = v.x; ish[c4*4+1][yy][xx] = v.y;
                ish[c4*4+2][yy][xx] = v.z; ish[c4*4+3][yy][xx] = v.w;
            }
        } else {
            for (int e = tid; e < CCH * (TY+2) * (TX+2); e += 128) {
                int ci = e / ((TY+2)*(TX+2));
                int rem = e - ci * ((TY+2)*(TX+2));
                int yy = rem / (TX+2), xx = rem - yy * (TX+2);
                int gy = by + yy - 1, gx = bx + xx - 1;
                float v = 0.f;
                if (gy >= 0 && gy < IMH && gx >= 0 && gx < IMW)
                    v = in[(long long)z * inZStr + (long long)(gy * IMW + gx) * inPixStr + cbase + ci];
                ish[ci][yy][xx] = v;
            }
        }
        // ---- stage weight chunk (HWIO), vectorized over cout ----
        {
            constexpr int W4N = 9 * CCH * (COUT / 4);
            for (int e = tid; e < W4N; e += 128) {
                int co4 = e % (COUT/4), r = e / (COUT/4);
                int tap = r / CCH, ci = r - tap * CCH;
                float4 v = *(const float4*)&wt[((long long)tap * CIN + cbase + ci) * COUT + co4*4];
                *(float4*)&wsh[tap][ci][co4*4] = v;
            }
        }
        __syncthreads();
#pragma unroll 2
        for (int ci = 0; ci < CCH; ci++) {
#pragma unroll
            for (int dy = 0; dy < 3; dy++) {
                const float* row = &ish[ci][py + dy][px0];
                float4 ra = *(const float4*)row;
                float2 rb = *(const float2*)(row + 4);
                ull v[6];
                v[0] = pk2(ra.x); v[1] = pk2(ra.y); v[2] = pk2(ra.z);
                v[3] = pk2(ra.w); v[4] = pk2(rb.x); v[5] = pk2(rb.y);
#pragma unroll
                for (int dxx = 0; dxx < 3; dxx++) {
                    const ulonglong2* wp = (const ulonglong2*)&wsh[dy*3 + dxx][ci][co0];
#pragma unroll
                    for (int h2 = 0; h2 < CO_H/2; h2++) {
                        ulonglong2 wv = wp[h2];
#pragma unroll
                        for (int p = 0; p < 4; p++) {
                            fma2(acc[p][2*h2],     v[p + dxx], wv.x);
                            fma2(acc[p][2*h2 + 1], v[p + dxx], wv.y);
                        }
                    }
                }
            }
        }
    }

    int gy = by + py;
    if constexpr (ACT != 2) {
#pragma unroll
        for (int p = 0; p < 4; p++) {
            int gx = bx + px0 + p;
            long long ob = (long long)z * outZStr + (long long)(gy * IMW + gx) * outPixStr
                         + outChOff + co0;
#pragma unroll
            for (int h = 0; h < CO_H; h += 2) {
                float2 o0 = upk(acc[p][h]);
                float2 o1 = upk(acc[p][h+1]);
                float c0 = o0.x + bias[co0 + 2*h],   c1 = o0.y + bias[co0 + 2*h + 1];
                float c2 = o1.x + bias[co0 + 2*h+2], c3 = o1.y + bias[co0 + 2*h + 3];
                if (ACT == 1) {
                    c0 = fmaxf(c0, 0.f); c1 = fmaxf(c1, 0.f);
                    c2 = fmaxf(c2, 0.f); c3 = fmaxf(c3, 0.f);
                }
                *(float4*)(out + ob + 2*h) = make_float4(c0, c1, c2, c3);
            }
        }
    } else {
        // sigmoid -> SMEM (reuse wsh), then per-pixel cumprod compositing
        __syncthreads();                       // everyone done reading wsh
        float* msh = &wsh[0][0][0];            // 128 pixels x stride 65
#pragma unroll
        for (int p = 0; p < 4; p++) {
            int lp = py * 16 + px0 + p;
#pragma unroll
            for (int h = 0; h < CO_H; h++) {
                float2 o = upk(acc[p][h]);
                msh[lp*65 + co0 + 2*h]     = 1.f / (1.f + __expf(-(o.x + bias[co0 + 2*h])));
                msh[lp*65 + co0 + 2*h + 1] = 1.f / (1.f + __expf(-(o.y + bias[co0 + 2*h + 1])));
            }
        }
        __syncthreads();
        int lp = tid;                          // 128 threads == 128 pixels
        int py2 = lp >> 4, px2 = lp & 15;
        int gy2 = by + py2, gx2 = bx + px2;
        const float* fr = fmp + ((long long)(z * IMH + gy2) * IMW + gx2) * 64;
        float a = 1.f, fs = 0.f;
#pragma unroll
        for (int c = 0; c < 64; c += 4) {
            float4 f = *(const float4*)(fr + c);
            float m0 = msh[lp*65 + c],     m1 = msh[lp*65 + c + 1];
            float m2 = msh[lp*65 + c + 2], m3 = msh[lp*65 + c + 3];
            fs += f.x * m0 * a; a *= (1.f - m0);
            fs += f.y * m1 * a; a *= (1.f - m1);
            fs += f.z * m2 * a; a *= (1.f - m2);
            fs += f.w * m3 * a; a *= (1.f - m3);
        }
        fusep[(long long)(gy2 * IMW + gx2) * NK + z] = fs;
    }
}

// ---------------------------------------------------------------------------
// Final tiny conv: 32 -> 3 (un2). One thread per pixel.
// ---------------------------------------------------------------------------
__global__ __launch_bounds__(256) void conv_small_kernel(
    const float* __restrict__ in, const float* __restrict__ wt,
    const float* __restrict__ bias, float* __restrict__ out)
{
    __shared__ float wsh[9 * 32 * 3];
    int tid = threadIdx.x;
    for (int e = tid; e < 9 * 32 * 3; e += 256) wsh[e] = wt[e];
    __syncthreads();
    int pix = blockIdx.x * 256 + tid;
    int gy = pix / IMW, gx = pix - gy * IMW;
    float a0 = bias[0], a1 = bias[1], a2 = bias[2];
#pragma unroll
    for (int dy = 0; dy < 3; dy++) {
        int iy = gy + dy - 1;
        if (iy < 0 || iy >= IMH) continue;
#pragma unroll
        for (int dxx = 0; dxx < 3; dxx++) {
            int ix = gx + dxx - 1;
            if (ix < 0 || ix >= IMW) continue;
            const float* ip = in + ((long long)iy * IMW + ix) * 32;
            const float* wp = &wsh[(dy*3 + dxx) * 32 * 3];
#pragma unroll
            for (int c4 = 0; c4 < 8; c4++) {
                float4 v = *(const float4*)(ip + c4*4);
                const float* w = wp + c4*12;
                a0 += v.x*w[0] + v.y*w[3] + v.z*w[6] + v.w*w[9];
                a1 += v.x*w[1] + v.y*w[4] + v.z*w[7] + v.w*w[10];
                a2 += v.x*w[2] + v.y*w[5] + v.z*w[8] + v.w*w[11];
            }
        }
    }
    out[(long long)pix * 3 + 0] = a0;
    out[(long long)pix * 3 + 1] = a1;
    out[(long long)pix * 3 + 2] = a2;
}

// ---------------------------------------------------------------------------
// Launcher
// ---------------------------------------------------------------------------
extern "C" void kernel_launch(void* const* d_in, const int* in_sizes, int n_in,
                              void* d_out, int out_size)
{
    (void)in_sizes; (void)n_in; (void)out_size;
    const float* colors = (const float*)d_in[0];
    const float* ray    = (const float*)d_in[1];
    const float* zbufs  = (const float*)d_in[2];
    const float* W1 = (const float*)d_in[3],  * b1 = (const float*)d_in[4];
    const float* W2 = (const float*)d_in[5],  * b2 = (const float*)d_in[6];
    const float* W3 = (const float*)d_in[7],  * b3 = (const float*)d_in[8];
    const float* W4 = (const float*)d_in[9],  * b4 = (const float*)d_in[10];
    const float* ks1 = (const float*)d_in[11], * bs1 = (const float*)d_in[12];
    const float* ks2 = (const float*)d_in[13], * bs2 = (const float*)d_in[14];
    const float* km1 = (const float*)d_in[15], * bm1 = (const float*)d_in[16];
    const float* km2 = (const float*)d_in[17], * bm2 = (const float*)d_in[18];
    const float* ku1 = (const float*)d_in[19], * bu1 = (const float*)d_in[20];
    const float* ku2 = (const float*)d_in[21], * bu2 = (const float*)d_in[22];
    float* out = (float*)d_out;

    float *t1, *fm, *t2, *fuse, *t3;
    cudaGetSymbolAddress((void**)&t1,   g_t1);
    cudaGetSymbolAddress((void**)&fm,   g_fm);
    cudaGetSymbolAddress((void**)&t2,   g_t2);
    cudaGetSymbolAddress((void**)&fuse, g_fuse);
    cudaGetSymbolAddress((void**)&t3,   g_t3);

    const long long P32 = (long long)IMH * IMW * 32;
    const long long P64 = (long long)IMH * IMW * 64;

    static int smem_set = 0;
    if (!smem_set) {
        cudaFuncSetAttribute(mlp_kernel, cudaFuncAttributeMaxDynamicSharedMemorySize,
                             2 * 64 * 136 * (int)sizeof(float));
        smem_set = 1;
    }
    mlp_kernel<<<dim3(IMW/64, IMH, NK), 256, 2 * 64 * 136 * sizeof(float)>>>(
        ray, zbufs, W1, b1, W2, b2, W3, b3, W4, b4, fm);

    dim3 cgrid(IMW/16, IMH/8, NK);
    // sup1: colors[k-slice] (3 ch) -> t1 (32 ch), relu
    conv3x3_kernel<3, 32, 1><<<cgrid, 128>>>(
        colors, ks1, bs1, t1, /*inZStr=*/3, /*inPixStr=*/3*NK,
        P32, 32, 0, nullptr, nullptr);
    // sup2: t1 -> fm[...,32:64], no act
    conv3x3_kernel<32, 32, 0><<<cgrid, 128>>>(
        t1, ks2, bs2, fm, P32, 32,
        P64, 64, 32, nullptr, nullptr);
    // mpn1: fm -> t2, relu
    conv3x3_kernel<64, 64, 1><<<cgrid, 128>>>(
        fm, km1, bm1, t2, P64, 64,
        P64, 64, 0, nullptr, nullptr);
    // mpn2: t2 -> sigmoid -> composite with fm -> fuse[H,W,K]
    conv3x3_kernel<64, 64, 2><<<cgrid, 128>>>(
        t2, km2, bm2, nullptr, P64, 64,
        0, 0, 0, fm, fuse);
    // un1: fuse (8 ch) -> t3 (32 ch), relu
    conv3x3_kernel<8, 32, 1><<<dim3(IMW/16, IMH/8, 1), 128>>>(
        fuse, ku1, bu1, t3, 0, NK,
        0, 32, 0, nullptr, nullptr);
    // un2: t3 -> out (3 ch)
    conv_small_kernel<<<(IMH*IMW)/256, 256>>>(t3, ku2, bu2, out);
}

// round 14
// speedup vs baseline: 1.2927x; 1.0083x over previous
#include <cuda_runtime.h>

// ---------------------------------------------------------------------------
// Problem constants
// ---------------------------------------------------------------------------
constexpr int IMH = 512;
constexpr int IMW = 512;
constexpr int NK  = 8;     // zbuf layers

typedef unsigned long long ull;

// ---------------------------------------------------------------------------
// f32x2 packed-FMA helpers (FFMA2: 2x fp32 FMA per issue slot on sm_103a)
// ---------------------------------------------------------------------------
__device__ __forceinline__ ull pk2(float v) {
    ull r; unsigned u = __float_as_uint(v);
    asm("mov.b64 %0, {%1, %1};" : "=l"(r) : "r"(u));
    return r;
}
__device__ __forceinline__ void fma2(ull& d, ull a, ull b) {
    asm("fma.rn.f32x2 %0, %1, %2, %0;" : "+l"(d) : "l"(a), "l"(b));
}
__device__ __forceinline__ float2 upk(ull v) {
    unsigned lo, hi;
    asm("mov.b64 {%0, %1}, %2;" : "=r"(lo), "=r"(hi) : "l"(v));
    return make_float2(__uint_as_float(lo), __uint_as_float(hi));
}

// ---------------------------------------------------------------------------
// Scratch buffers (static device globals -- no cudaMalloc allowed)
// ---------------------------------------------------------------------------
__device__ float g_t1[(size_t)NK * IMH * IMW * 32];   // sup1 out
__device__ float g_fm[(size_t)NK * IMH * IMW * 64];   // [fz | fc]
__device__ float g_t2[(size_t)NK * IMH * IMW * 64];   // mpn1 out
__device__ float g_fuse[(size_t)IMH * IMW * NK];      // fused img
__device__ float g_t3[(size_t)IMH * IMW * 32];        // un1 out

// ---------------------------------------------------------------------------
// Fused 4-layer MLP. One block = 64 consecutive x for fixed (k, y).
// ---------------------------------------------------------------------------
template<int KIN, bool RELU>
__device__ __forceinline__ void mlp_layer128(const float* __restrict__ bufIn,
                                             float* __restrict__ bufOut,
                                             const float* __restrict__ Wg,
                                             const float* __restrict__ bg, int tid)
{
    int jg = tid & 15, pg = tid >> 4;       // 16 j-groups x 16 p-groups
    int j0 = jg * 8,  p0 = pg * 4;          // 8 outputs x 4 points per thread
    ull acc[4][4];
    ulonglong2 bb0 = *(const ulonglong2*)(bg + j0);
    ulonglong2 bb1 = *(const ulonglong2*)(bg + j0 + 4);
#pragma unroll
    for (int i = 0; i < 4; i++) { acc[i][0]=bb0.x; acc[i][1]=bb0.y; acc[i][2]=bb1.x; acc[i][3]=bb1.y; }

    constexpr int KV = KIN & ~3;            // vectorized portion
#pragma unroll 2
    for (int kk = 0; kk < KV; kk += 4) {
        float4 a[4];
#pragma unroll
        for (int i = 0; i < 4; i++)
            a[i] = *(const float4*)&bufIn[(p0+i)*136 + kk];
#pragma unroll
        for (int q = 0; q < 4; q++) {
            ulonglong2 w0 = *(const ulonglong2*)(Wg + (kk+q)*128 + j0);
            ulonglong2 w1 = *(const ulonglong2*)(Wg + (kk+q)*128 + j0 + 4);
#pragma unroll
            for (int i = 0; i < 4; i++) {
                float s = (q==0) ? a[i].x : (q==1) ? a[i].y : (q==2) ? a[i].z : a[i].w;
                ull av = pk2(s);
                fma2(acc[i][0], av, w0.x); fma2(acc[i][1], av, w0.y);
                fma2(acc[i][2], av, w1.x); fma2(acc[i][3], av, w1.y);
            }
        }
    }
#pragma unroll
    for (int kk = KV; kk < KIN; kk++) {     // scalar tail (KIN=3 or 131)
        ulonglong2 w0 = *(const ulonglong2*)(Wg + kk*128 + j0);
        ulonglong2 w1 = *(const ulonglong2*)(Wg + kk*128 + j0 + 4);
#pragma unroll
        for (int i = 0; i < 4; i++) {
            ull av = pk2(bufIn[(p0+i)*136 + kk]);
            fma2(acc[i][0], av, w0.x); fma2(acc[i][1], av, w0.y);
            fma2(acc[i][2], av, w1.x); fma2(acc[i][3], av, w1.y);
        }
    }
#pragma unroll
    for (int i = 0; i < 4; i++) {
        float* orow = bufOut + (p0+i)*136 + j0;
#pragma unroll
        for (int h = 0; h < 4; h += 2) {
            float2 o0 = upk(acc[i][h]);
            float2 o1 = upk(acc[i][h+1]);
            if (RELU) {
                o0.x = fmaxf(o0.x, 0.f); o0.y = fmaxf(o0.y, 0.f);
                o1.x = fmaxf(o1.x, 0.f); o1.y = fmaxf(o1.y, 0.f);
            }
            *(float4*)(orow + 2*h) = make_float4(o0.x, o0.y, o1.x, o1.y);
        }
    }
}

__global__ __launch_bounds__(256, 3) void mlp_kernel(
    const float* __restrict__ ray, const float* __restrict__ zbufs,
    const float* __restrict__ W1, const float* __restrict__ b1,
    const float* __restrict__ W2, const float* __restrict__ b2,
    const float* __restrict__ W3, const float* __restrict__ b3,
    const float* __restrict__ W4, const float* __restrict__ b4,
    float* __restrict__ fm)
{
    extern __shared__ float sm[];
    float* bufA = sm;
    float* bufB = sm + 64 * 136;
    int tid = threadIdx.x;
    int x0 = blockIdx.x * 64, y = blockIdx.y, k = blockIdx.z;

    if (tid < 64) {
        int x = x0 + tid;
        const float* r = ray + ((long long)y * IMW + x) * 7;
        float dx = r[3], dy = r[4], dz = r[5];
        float z = zbufs[((long long)y * IMW + x) * NK + k];
        float t = z / r[6];
        float* row = bufA + tid * 136;
        row[0] = r[0] + dx * t; row[1] = r[1] + dy * t; row[2] = r[2] + dz * t;
        row[128] = dx; row[129] = dy; row[130] = dz; row[131] = z;
    }
    __syncthreads();
    mlp_layer128<3,   true>(bufA, bufB, W1, b1, tid);
    __syncthreads();
    mlp_layer128<128, true>(bufB, bufA, W2, b2, tid);   // dirs/z at 128..131 survive
    __syncthreads();
    mlp_layer128<131, true>(bufA, bufB, W3, b3, tid);   // concat([h, dirs]) @ W3
    __syncthreads();
    {   // layer 4: 128 -> 32, no relu, masked vectorized write to fm[...,0:32]
        int jg = tid & 3, p = tid >> 2;
        int j0 = jg * 8;
        ull acc[4];
        ulonglong2 bb0 = *(const ulonglong2*)(b4 + j0);
        ulonglong2 bb1 = *(const ulonglong2*)(b4 + j0 + 4);
        acc[0] = bb0.x; acc[1] = bb0.y; acc[2] = bb1.x; acc[3] = bb1.y;
        const float* rowi = bufB + p * 136;
#pragma unroll 2
        for (int kk = 0; kk < 128; kk += 4) {
            float4 a = *(const float4*)(rowi + kk);
#pragma unroll
            for (int q = 0; q < 4; q++) {
                ulonglong2 w0 = *(const ulonglong2*)(W4 + (kk+q)*32 + j0);
                ulonglong2 w1 = *(const ulonglong2*)(W4 + (kk+q)*32 + j0 + 4);
                float s = (q==0) ? a.x : (q==1) ? a.y : (q==2) ? a.z : a.w;
                ull av = pk2(s);
                fma2(acc[0], av, w0.x); fma2(acc[1], av, w0.y);
                fma2(acc[2], av, w1.x); fma2(acc[3], av, w1.y);
            }
        }
        bool live = bufA[p*136 + 131] > 0.f;
        long long ob = ((long long)(k * IMH + y) * IMW + x0 + p) * 64 + j0;
        float2 o0 = upk(acc[0]), o1 = upk(acc[1]), o2 = upk(acc[2]), o3 = upk(acc[3]);
        float4 v0 = live ? make_float4(o0.x, o0.y, o1.x, o1.y) : make_float4(0,0,0,0);
        float4 v1 = live ? make_float4(o2.x, o2.y, o3.x, o3.y) : make_float4(0,0,0,0);
        *(float4*)(fm + ob)     = v0;
        *(float4*)(fm + ob + 4) = v1;
    }
}

// ---------------------------------------------------------------------------
// Generic 3x3 SAME conv, NHWC, register-tiled. 16x8 tile, 128 threads.
// COUT=64: 8 cout-groups x 16 pixel-groups, 8 px/thread  (weight LDS halved)
// COUT=32: 4 cout-groups x 32 pixel-groups, 4 px/thread  (as before)
// ACT: 0 = none, 1 = relu, 2 = sigmoid + cumprod-composite epilogue.
// ---------------------------------------------------------------------------
template<int CIN, int COUT, int ACT>
__global__ __launch_bounds__(128, 4) void conv3x3_kernel(
    const float* __restrict__ in, const float* __restrict__ wt,
    const float* __restrict__ bias, float* __restrict__ out,
    long long inZStr, int inPixStr,
    long long outZStr, int outPixStr, int outChOff,
    const float* __restrict__ fmp, float* __restrict__ fusep)
{
    constexpr int TX = 16, TY = 8;
    constexpr int CCH = (CIN < 16) ? CIN : 16;
    constexpr int NCH = CIN / CCH;
    constexpr int NPX   = (COUT == 64) ? 8 : 4;       // pixels per thread
    constexpr int NPIXG = (TX / NPX) * TY;            // 16 or 32 pixel-groups
    constexpr int NCOG  = 128 / NPIXG;                // 8 or 4 cout-groups
    constexpr int CO_T  = COUT / NCOG;                // 8 in both cases
    constexpr int CO_H  = CO_T / 2;                   // 4 f32x2 pairs
    constexpr int TPR   = TX / NPX;                   // threads per row
    constexpr int XPAD  = 24;                         // padded halo row

    __shared__ __align__(16) float ish[CCH][TY+2][XPAD];
    __shared__ __align__(16) float wsh[9][CCH][COUT];

    int tid = threadIdx.x;
    int z = blockIdx.z;
    int bx = blockIdx.x * TX, by = blockIdx.y * TY;
    int cog = tid / NPIXG, pixg = tid % NPIXG;
    int px0 = (pixg % TPR) * NPX, py = pixg / TPR;
    int co0 = cog * CO_T;

    ull acc[NPX][CO_H];
#pragma unroll
    for (int p = 0; p < NPX; p++)
#pragma unroll
        for (int h = 0; h < CO_H; h++) acc[p][h] = 0ULL;

#pragma unroll 1
    for (int ch = 0; ch < NCH; ch++) {
        int cbase = ch * CCH;
        if (ch > 0) __syncthreads();
        // ---- stage input tile (with halo, zero-padded at borders) ----
        if constexpr (CCH % 4 == 0) {
            constexpr int C4 = CCH / 4;
            for (int e = tid; e < (TY+2)*(TX+2)*C4; e += 128) {
                int c4 = e % C4, pix = e / C4;
                int yy = pix / (TX+2), xx = pix - yy * (TX+2);
                int gy = by + yy - 1, gx = bx + xx - 1;
                float4 v = make_float4(0.f, 0.f, 0.f, 0.f);
                if (gy >= 0 && gy < IMH && gx >= 0 && gx < IMW)
                    v = *(const float4*)&in[(long long)z * inZStr
                        + (long long)(gy * IMW + gx) * inPixStr + cbase + c4*4];
                ish[c4*4+0][yy][xx] = v.x; ish[c4*4+1][yy][xx] = v.y;
                ish[c4*4+2][yy][xx] = v.z; ish[c4*4+3][yy][xx] = v.w;
            }
        } else {
            for (int e = tid; e < CCH * (TY+2) * (TX+2); e += 128) {
                int ci = e / ((TY+2)*(TX+2));
                int rem = e - ci * ((TY+2)*(TX+2));
                int yy = rem / (TX+2), xx = rem - yy * (TX+2);
                int gy = by + yy - 1, gx = bx + xx - 1;
                float v = 0.f;
                if (gy >= 0 && gy < IMH && gx >= 0 && gx < IMW)
                    v = in[(long long)z * inZStr + (long long)(gy * IMW + gx) * inPixStr + cbase + ci];
                ish[ci][yy][xx] = v;
            }
        }
        // ---- stage weight chunk (HWIO), vectorized over cout ----
        {
            constexpr int W4N = 9 * CCH * (COUT / 4);
            for (int e = tid; e < W4N; e += 128) {
                int co4 = e % (COUT/4), r = e / (COUT/4);
                int tap = r / CCH, ci = r - tap * CCH;
                float4 v = *(const float4*)&wt[((long long)tap * CIN + cbase + ci) * COUT + co4*4];
                *(float4*)&wsh[tap][ci][co4*4] = v;
            }
        }
        __syncthreads();
#pragma unroll 2
        for (int ci = 0; ci < CCH; ci++) {
#pragma unroll
            for (int dy = 0; dy < 3; dy++) {
                const float* row = &ish[ci][py + dy][px0];
                ull v[NPX + 2];
#pragma unroll
                for (int m = 0; m < ((NPX+2)/4)*4; m += 4) {
                    float4 t = *(const float4*)(row + m);
                    v[m+0] = pk2(t.x); v[m+1] = pk2(t.y);
                    v[m+2] = pk2(t.z); v[m+3] = pk2(t.w);
                }
                {
                    float2 t = *(const float2*)(row + ((NPX+2)/4)*4);
                    v[NPX+0] = pk2(t.x); v[NPX+1] = pk2(t.y);
                }
#pragma unroll
                for (int dxx = 0; dxx < 3; dxx++) {
                    const ulonglong2* wp = (const ulonglong2*)&wsh[dy*3 + dxx][ci][co0];
#pragma unroll
                    for (int h2 = 0; h2 < CO_H/2; h2++) {
                        ulonglong2 wv = wp[h2];
#pragma unroll
                        for (int p = 0; p < NPX; p++) {
                            fma2(acc[p][2*h2],     v[p + dxx], wv.x);
                            fma2(acc[p][2*h2 + 1], v[p + dxx], wv.y);
                        }
                    }
                }
            }
        }
    }

    int gy = by + py;
    if constexpr (ACT != 2) {
#pragma unroll
        for (int p = 0; p < NPX; p++) {
            int gx = bx + px0 + p;
            long long ob = (long long)z * outZStr + (long long)(gy * IMW + gx) * outPixStr
                         + outChOff + co0;
#pragma unroll
            for (int h = 0; h < CO_H; h += 2) {
                float2 o0 = upk(acc[p][h]);
                float2 o1 = upk(acc[p][h+1]);
                float c0 = o0.x + bias[co0 + 2*h],   c1 = o0.y + bias[co0 + 2*h + 1];
                float c2 = o1.x + bias[co0 + 2*h+2], c3 = o1.y + bias[co0 + 2*h + 3];
                if (ACT == 1) {
                    c0 = fmaxf(c0, 0.f); c1 = fmaxf(c1, 0.f);
                    c2 = fmaxf(c2, 0.f); c3 = fmaxf(c3, 0.f);
                }
                *(float4*)(out + ob + 2*h) = make_float4(c0, c1, c2, c3);
            }
        }
    } else {
        // sigmoid -> SMEM (reuse wsh), then per-pixel cumprod compositing
        __syncthreads();                       // everyone done reading wsh
        float* msh = &wsh[0][0][0];            // 128 pixels x stride 65
#pragma unroll
        for (int p = 0; p < NPX; p++) {
            int lp = py * 16 + px0 + p;
#pragma unroll
            for (int h = 0; h < CO_H; h++) {
                float2 o = upk(acc[p][h]);
                msh[lp*65 + co0 + 2*h]     = 1.f / (1.f + __expf(-(o.x + bias[co0 + 2*h])));
                msh[lp*65 + co0 + 2*h + 1] = 1.f / (1.f + __expf(-(o.y + bias[co0 + 2*h + 1])));
            }
        }
        __syncthreads();
        int lp = tid;                          // 128 threads == 128 pixels
        int py2 = lp >> 4, px2 = lp & 15;
        int gy2 = by + py2, gx2 = bx + px2;
        const float* fr = fmp + ((long long)(z * IMH + gy2) * IMW + gx2) * 64;
        float a = 1.f, fs = 0.f;
#pragma unroll
        for (int c = 0; c < 64; c += 4) {
            float4 f = *(const float4*)(fr + c);
            float m0 = msh[lp*65 + c],     m1 = msh[lp*65 + c + 1];
            float m2 = msh[lp*65 + c + 2], m3 = msh[lp*65 + c + 3];
            fs += f.x * m0 * a; a *= (1.f - m0);
            fs += f.y * m1 * a; a *= (1.f - m1);
            fs += f.z * m2 * a; a *= (1.f - m2);
            fs += f.w * m3 * a; a *= (1.f - m3);
        }
        fusep[(long long)(gy2 * IMW + gx2) * NK + z] = fs;
    }
}

// ---------------------------------------------------------------------------
// Final tiny conv: 32 -> 3 (un2). One thread per pixel.
// ---------------------------------------------------------------------------
__global__ __launch_bounds__(256) void conv_small_kernel(
    const float* __restrict__ in, const float* __restrict__ wt,
    const float* __restrict__ bias, float* __restrict__ out)
{
    __shared__ float wsh[9 * 32 * 3];
    int tid = threadIdx.x;
    for (int e = tid; e < 9 * 32 * 3; e += 256) wsh[e] = wt[e];
    __syncthreads();
    int pix = blockIdx.x * 256 + tid;
    int gy = pix / IMW, gx = pix - gy * IMW;
    float a0 = bias[0], a1 = bias[1], a2 = bias[2];
#pragma unroll
    for (int dy = 0; dy < 3; dy++) {
        int iy = gy + dy - 1;
        if (iy < 0 || iy >= IMH) continue;
#pragma unroll
        for (int dxx = 0; dxx < 3; dxx++) {
            int ix = gx + dxx - 1;
            if (ix < 0 || ix >= IMW) continue;
            const float* ip = in + ((long long)iy * IMW + ix) * 32;
            const float* wp = &wsh[(dy*3 + dxx) * 32 * 3];
#pragma unroll
            for (int c4 = 0; c4 < 8; c4++) {
                float4 v = *(const float4*)(ip + c4*4);
                const float* w = wp + c4*12;
                a0 += v.x*w[0] + v.y*w[3] + v.z*w[6] + v.w*w[9];
                a1 += v.x*w[1] + v.y*w[4] + v.z*w[7] + v.w*w[10];
                a2 += v.x*w[2] + v.y*w[5] + v.z*w[8] + v.w*w[11];
            }
        }
    }
    out[(long long)pix * 3 + 0] = a0;
    out[(long long)pix * 3 + 1] = a1;
    out[(long long)pix * 3 + 2] = a2;
}

// ---------------------------------------------------------------------------
// Launcher
// ---------------------------------------------------------------------------
extern "C" void kernel_launch(void* const* d_in, const int* in_sizes, int n_in,
                              void* d_out, int out_size)
{
    (void)in_sizes; (void)n_in; (void)out_size;
    const float* colors = (const float*)d_in[0];
    const float* ray    = (const float*)d_in[1];
    const float* zbufs  = (const float*)d_in[2];
    const float* W1 = (const float*)d_in[3],  * b1 = (const float*)d_in[4];
    const float* W2 = (const float*)d_in[5],  * b2 = (const float*)d_in[6];
    const float* W3 = (const float*)d_in[7],  * b3 = (const float*)d_in[8];
    const float* W4 = (const float*)d_in[9],  * b4 = (const float*)d_in[10];
    const float* ks1 = (const float*)d_in[11], * bs1 = (const float*)d_in[12];
    const float* ks2 = (const float*)d_in[13], * bs2 = (const float*)d_in[14];
    const float* km1 = (const float*)d_in[15], * bm1 = (const float*)d_in[16];
    const float* km2 = (const float*)d_in[17], * bm2 = (const float*)d_in[18];
    const float* ku1 = (const float*)d_in[19], * bu1 = (const float*)d_in[20];
    const float* ku2 = (const float*)d_in[21], * bu2 = (const float*)d_in[22];
    float* out = (float*)d_out;

    float *t1, *fm, *t2, *fuse, *t3;
    cudaGetSymbolAddress((void**)&t1,   g_t1);
    cudaGetSymbolAddress((void**)&fm,   g_fm);
    cudaGetSymbolAddress((void**)&t2,   g_t2);
    cudaGetSymbolAddress((void**)&fuse, g_fuse);
    cudaGetSymbolAddress((void**)&t3,   g_t3);

    const long long P32 = (long long)IMH * IMW * 32;
    const long long P64 = (long long)IMH * IMW * 64;

    static int smem_set = 0;
    if (!smem_set) {
        cudaFuncSetAttribute(mlp_kernel, cudaFuncAttributeMaxDynamicSharedMemorySize,
                             2 * 64 * 136 * (int)sizeof(float));
        smem_set = 1;
    }
    mlp_kernel<<<dim3(IMW/64, IMH, NK), 256, 2 * 64 * 136 * sizeof(float)>>>(
        ray, zbufs, W1, b1, W2, b2, W3, b3, W4, b4, fm);

    dim3 cgrid(IMW/16, IMH/8, NK);
    // sup1: colors[k-slice] (3 ch) -> t1 (32 ch), relu
    conv3x3_kernel<3, 32, 1><<<cgrid, 128>>>(
        colors, ks1, bs1, t1, /*inZStr=*/3, /*inPixStr=*/3*NK,
        P32, 32, 0, nullptr, nullptr);
    // sup2: t1 -> fm[...,32:64], no act
    conv3x3_kernel<32, 32, 0><<<cgrid, 128>>>(
        t1, ks2, bs2, fm, P32, 32,
        P64, 64, 32, nullptr, nullptr);
    // mpn1: fm -> t2, relu
    conv3x3_kernel<64, 64, 1><<<cgrid, 128>>>(
        fm, km1, bm1, t2, P64, 64,
        P64, 64, 0, nullptr, nullptr);
    // mpn2: t2 -> sigmoid -> composite with fm -> fuse[H,W,K]
    conv3x3_kernel<64, 64, 2><<<cgrid, 128>>>(
        t2, km2, bm2, nullptr, P64, 64,
        0, 0, 0, fm, fuse);
    // un1: fuse (8 ch) -> t3 (32 ch), relu
    conv3x3_kernel<8, 32, 1><<<dim3(IMW/16, IMH/8, 1), 128>>>(
        fuse, ku1, bu1, t3, 0, NK,
        0, 32, 0, nullptr, nullptr);
    // un2: t3 -> out (3 ch)
    conv_small_kernel<<<(IMH*IMW)/256, 256>>>(t3, ku2, bu2, out);
}